// round 14
// baseline (speedup 1.0000x reference)
#include <cuda_runtime.h>
#include <cstdint>

#define N_NODES 100000
#define D_IN 128
#define D_HID 256
#define D_OUT 128
#define N_EDGES 1600000
#define NSM 148
#define SCAN_B 512
#define SCAN_NB ((N_NODES + SCAN_B - 1) / SCAN_B)

// Scratch (static __device__ arrays — no runtime allocation).
__device__ int    g_row[N_NODES + 1];             // CSR row starts
__device__ int    g_cursor[N_NODES];              // fill cursors
__device__ int    g_part[SCAN_NB];                // scan partials
__device__ int    g_srcS[N_EDGES];                // src sorted by dst
__device__ float  g_valS[N_EDGES];                // val sorted by dst
__device__ float2 g_W1f[(D_IN  / 8) * (D_HID / 8) * 32];  // W1 fragment-packed
__device__ float2 g_W2f[(D_HID / 8) * (D_OUT / 8) * 32];  // W2 fragment-packed

__device__ __forceinline__ float f2tf32(float f) {
    uint32_t r;
    asm("cvt.rna.tf32.f32 %0, %1;" : "=r"(r) : "f"(f));
    return __uint_as_float(r);
}

// ---------------------------------------------------------------------------
// K0: zero histogram counters + pack W1/W2 into MMA B-fragment order (tf32).
// ---------------------------------------------------------------------------
__global__ void k_zero_pack(const float* __restrict__ W1,
                            const float* __restrict__ W2) {
    int i = blockIdx.x * blockDim.x + threadIdx.x;
    if (i < N_NODES) g_row[i] = 0;
    constexpr int NB1c = D_HID / 8;  // 32
    constexpr int KB1c = D_IN  / 8;  // 16
    constexpr int NB2c = D_OUT / 8;  // 16
    constexpr int KB2c = D_HID / 8;  // 32
    if (i < KB1c * NB1c * 32) {
        int l   = i & 31;
        int n8  = (i >> 5) % NB1c;
        int k8  = (i >> 5) / NB1c;
        int col = n8 * 8 + (l >> 2);
        int r0  = k8 * 8 + (l & 3);
        float2 v;
        v.x = f2tf32(__ldg(W1 + r0 * D_HID + col));
        v.y = f2tf32(__ldg(W1 + (r0 + 4) * D_HID + col));
        g_W1f[i] = v;
    }
    if (i < KB2c * NB2c * 32) {
        int l   = i & 31;
        int n8  = (i >> 5) % NB2c;
        int k8  = (i >> 5) / NB2c;
        int col = n8 * 8 + (l >> 2);
        int r0  = k8 * 8 + (l & 3);
        float2 v;
        v.x = f2tf32(__ldg(W2 + r0 * D_OUT + col));
        v.y = f2tf32(__ldg(W2 + (r0 + 4) * D_OUT + col));
        g_W2f[i] = v;
    }
}

__global__ void k_hist(const int* __restrict__ dst) {
    int e = blockIdx.x * blockDim.x + threadIdx.x;
    if (e < N_EDGES) atomicAdd(&g_row[__ldg(dst + e)], 1);
}

__global__ void k_scan1() {   // per-block exclusive scan + block totals
    __shared__ int sm[SCAN_B];
    int i = blockIdx.x * SCAN_B + threadIdx.x;
    int v = (i < N_NODES) ? g_row[i] : 0;
    sm[threadIdx.x] = v;
    __syncthreads();
    for (int off = 1; off < SCAN_B; off <<= 1) {
        int t = (threadIdx.x >= off) ? sm[threadIdx.x - off] : 0;
        __syncthreads();
        sm[threadIdx.x] += t;
        __syncthreads();
    }
    if (i < N_NODES) g_row[i] = sm[threadIdx.x] - v;   // exclusive
    if (threadIdx.x == SCAN_B - 1) g_part[blockIdx.x] = sm[SCAN_B - 1];
}

// scan of g_part folded in: every block redundantly exclusive-scans the
// SCAN_NB partials in smem (read-only on g_part -> no race), then adds base.
__global__ void k_scan23() {
    __shared__ int sp[256];
    int t = threadIdx.x;
    int v = (t < SCAN_NB) ? g_part[t] : 0;
    sp[t] = v;
    __syncthreads();
    for (int off = 1; off < 256; off <<= 1) {
        int u = (t >= off) ? sp[t - off] : 0;
        __syncthreads();
        sp[t] += u;
        __syncthreads();
    }
    __shared__ int exc[SCAN_NB];
    if (t < SCAN_NB) exc[t] = sp[t] - v;
    __syncthreads();

    int i = blockIdx.x * blockDim.x + t;
    if (i < N_NODES) {
        int val = g_row[i] + exc[i / SCAN_B];
        g_row[i] = val;
        g_cursor[i] = val;
    }
    if (i == 0) g_row[N_NODES] = N_EDGES;
}

__global__ void k_fill(const int* __restrict__ src,
                       const int* __restrict__ dst,
                       const float* __restrict__ ev) {
    int e = blockIdx.x * blockDim.x + threadIdx.x;
    if (e >= N_EDGES) return;
    int d   = __ldg(dst + e);
    int pos = atomicAdd(&g_cursor[d], 1);
    g_srcS[pos] = __ldg(src + e);
    g_valS[pos] = __ldg(ev + e);
}

// ---------------------------------------------------------------------------
// Fused gather + MLP, 2 CTAs/SM:
//   Phase 0: CSR gather (AX row for 64 nodes) -> As smem (tf32), no g_AX.
//   Phase 1: As @ W1 (frags streamed from L2) -> relu+bias -> Hs smem.
//   Phase 2: Hs @ W2 (frags streamed from L2) -> out.
// Gather (L2/LSU-bound) overlaps MMA (tensor-bound) across the 2 CTAs/SM.
// ---------------------------------------------------------------------------
#define K1 D_IN        // 128
#define NH D_HID       // 256
#define NO D_OUT       // 128
#define BMT 64
#define SA1 (K1 + 4)   // 132
#define KB1 (K1 / 8)   // 16
#define NB1 (NH / 8)   // 32
#define KB2 (NH / 8)   // 32
#define NB2 (NO / 8)   // 16

__global__ __launch_bounds__(256, 2)
void fused_mlp(const float* __restrict__ x,
               const float* __restrict__ eps,
               const float* __restrict__ b1,
               const float* __restrict__ b2,
               float* __restrict__ out, int M) {
    extern __shared__ float sm[];
    float* As = sm;                    // 64 x 132
    float* Hs = sm + BMT * SA1;        // 64 x 256 (swizzled)

    const int tid  = threadIdx.x;
    const int lane = tid & 31;
    const int g    = lane >> 2, tig = lane & 3;
    const int wid  = tid >> 5;
    const int wm   = wid >> 2, wn = wid & 3;

    const float sl = 1.0f + eps[0];
    const int nTiles = (M + BMT - 1) / BMT;

    for (int tile = blockIdx.x; tile < nTiles; tile += gridDim.x) {
        const int m0 = tile * BMT;

        // ========== Phase 0: CSR gather -> As (tf32) ==========
        // Warp w handles rows [w*8, w*8+8). 4-edge unrolled float4 gathers.
#pragma unroll 1
        for (int j = 0; j < 8; j++) {
            int row = wid * 8 + j;
            int n   = m0 + row;
            float4 acc = make_float4(0.f, 0.f, 0.f, 0.f);
            if (n < M) {
                acc = *(const float4*)(x + (size_t)n * K1 + lane * 4);
                acc.x *= sl; acc.y *= sl; acc.z *= sl; acc.w *= sl;
                int e   = __ldg(&g_row[n]);
                int end = __ldg(&g_row[n + 1]);
                for (; e + 3 < end; e += 4) {
                    int   s0 = __ldg(g_srcS + e),     s1 = __ldg(g_srcS + e + 1);
                    int   s2 = __ldg(g_srcS + e + 2), s3 = __ldg(g_srcS + e + 3);
                    float v0 = __ldg(g_valS + e),     v1 = __ldg(g_valS + e + 1);
                    float v2 = __ldg(g_valS + e + 2), v3 = __ldg(g_valS + e + 3);
                    float4 a = *(const float4*)(x + (size_t)s0 * K1 + lane * 4);
                    float4 b = *(const float4*)(x + (size_t)s1 * K1 + lane * 4);
                    float4 c = *(const float4*)(x + (size_t)s2 * K1 + lane * 4);
                    float4 d = *(const float4*)(x + (size_t)s3 * K1 + lane * 4);
                    acc.x += v0 * a.x + v1 * b.x + v2 * c.x + v3 * d.x;
                    acc.y += v0 * a.y + v1 * b.y + v2 * c.y + v3 * d.y;
                    acc.z += v0 * a.z + v1 * b.z + v2 * c.z + v3 * d.z;
                    acc.w += v0 * a.w + v1 * b.w + v2 * c.w + v3 * d.w;
                }
                for (; e < end; e++) {
                    int   s0 = __ldg(g_srcS + e);
                    float v0 = __ldg(g_valS + e);
                    float4 a = *(const float4*)(x + (size_t)s0 * K1 + lane * 4);
                    acc.x += v0 * a.x; acc.y += v0 * a.y;
                    acc.z += v0 * a.z; acc.w += v0 * a.w;
                }
            }
            float* p = As + row * SA1 + lane * 4;
            p[0] = f2tf32(acc.x); p[1] = f2tf32(acc.y);
            p[2] = f2tf32(acc.z); p[3] = f2tf32(acc.w);
        }
        __syncthreads();

        // ================= Phase 1: H = relu(As@W1 + b1) =================
        {
            float c1[2][8][4];
#pragma unroll
            for (int mt = 0; mt < 2; mt++)
#pragma unroll
                for (int nt = 0; nt < 8; nt++) {
                    c1[mt][nt][0] = 0.f; c1[mt][nt][1] = 0.f;
                    c1[mt][nt][2] = 0.f; c1[mt][nt][3] = 0.f;
                }
            const int rbase = wm * 32 + g;

            float2 wbuf[8], wnext[8];
#pragma unroll
            for (int nt = 0; nt < 8; nt++)
                wbuf[nt] = __ldg(&g_W1f[(0 * NB1 + wn * 8 + nt) * 32 + lane]);

#pragma unroll 2
            for (int k8 = 0; k8 < KB1; k8++) {
                const int kk = k8 * 8;
                uint32_t a[2][4];
#pragma unroll
                for (int mt = 0; mt < 2; mt++) {
                    int r0 = rbase + mt * 16;
                    a[mt][0] = __float_as_uint(As[ r0      * SA1 + kk     + tig]);
                    a[mt][1] = __float_as_uint(As[(r0 + 8) * SA1 + kk     + tig]);
                    a[mt][2] = __float_as_uint(As[ r0      * SA1 + kk + 4 + tig]);
                    a[mt][3] = __float_as_uint(As[(r0 + 8) * SA1 + kk + 4 + tig]);
                }
                int k8n = (k8 + 1 < KB1) ? k8 + 1 : k8;
#pragma unroll
                for (int nt = 0; nt < 8; nt++)
                    wnext[nt] = __ldg(&g_W1f[(k8n * NB1 + wn * 8 + nt) * 32 + lane]);
#pragma unroll
                for (int nt = 0; nt < 8; nt++) {
                    uint32_t b0 = __float_as_uint(wbuf[nt].x);
                    uint32_t b1r = __float_as_uint(wbuf[nt].y);
#pragma unroll
                    for (int mt = 0; mt < 2; mt++) {
                        asm volatile(
                            "mma.sync.aligned.m16n8k8.row.col.f32.tf32.tf32.f32 "
                            "{%0,%1,%2,%3}, {%4,%5,%6,%7}, {%8,%9}, {%0,%1,%2,%3};"
                            : "+f"(c1[mt][nt][0]), "+f"(c1[mt][nt][1]),
                              "+f"(c1[mt][nt][2]), "+f"(c1[mt][nt][3])
                            : "r"(a[mt][0]), "r"(a[mt][1]),
                              "r"(a[mt][2]), "r"(a[mt][3]), "r"(b0), "r"(b1r));
                    }
                }
#pragma unroll
                for (int nt = 0; nt < 8; nt++) wbuf[nt] = wnext[nt];
            }
            // relu + bias -> Hs (tf32, swizzled: phys col = col ^ ((row&7)<<2))
#pragma unroll
            for (int mt = 0; mt < 2; mt++) {
#pragma unroll
                for (int nt = 0; nt < 8; nt++) {
                    int col = wn * 64 + nt * 8 + 2 * tig;
                    float bx = __ldg(b1 + col), by = __ldg(b1 + col + 1);
                    float v0 = fmaxf(c1[mt][nt][0] + bx, 0.f);
                    float v1 = fmaxf(c1[mt][nt][1] + by, 0.f);
                    float v2 = fmaxf(c1[mt][nt][2] + bx, 0.f);
                    float v3 = fmaxf(c1[mt][nt][3] + by, 0.f);
                    int r0 = wm * 32 + mt * 16 + g;      // row&7 == g
                    int r1 = r0 + 8;
                    *(float2*)(Hs + r0 * NH + (col ^ (g << 2))) =
                        make_float2(f2tf32(v0), f2tf32(v1));
                    *(float2*)(Hs + r1 * NH + (col ^ (g << 2))) =
                        make_float2(f2tf32(v2), f2tf32(v3));
                }
            }
        }
        __syncthreads();

        // ================= Phase 2: out = Hs@W2 + b2 =================
        {
            float c2[2][4][4];
#pragma unroll
            for (int mt = 0; mt < 2; mt++)
#pragma unroll
                for (int nt = 0; nt < 4; nt++) {
                    c2[mt][nt][0] = 0.f; c2[mt][nt][1] = 0.f;
                    c2[mt][nt][2] = 0.f; c2[mt][nt][3] = 0.f;
                }
            const int rbase = wm * 32 + g;

            float2 wbuf[4], wnext[4];
#pragma unroll
            for (int nt = 0; nt < 4; nt++)
                wbuf[nt] = __ldg(&g_W2f[(0 * NB2 + wn * 4 + nt) * 32 + lane]);

#pragma unroll 4
            for (int k8 = 0; k8 < KB2; k8++) {
                const int kk = k8 * 8;
                uint32_t a[2][4];
#pragma unroll
                for (int mt = 0; mt < 2; mt++) {
                    int r0 = rbase + mt * 16;
                    int sw = (g << 2);
                    a[mt][0] = __float_as_uint(Hs[ r0      * NH + ((kk     + tig) ^ sw)]);
                    a[mt][1] = __float_as_uint(Hs[(r0 + 8) * NH + ((kk     + tig) ^ sw)]);
                    a[mt][2] = __float_as_uint(Hs[ r0      * NH + ((kk + 4 + tig) ^ sw)]);
                    a[mt][3] = __float_as_uint(Hs[(r0 + 8) * NH + ((kk + 4 + tig) ^ sw)]);
                }
                int k8n = (k8 + 1 < KB2) ? k8 + 1 : k8;
#pragma unroll
                for (int nt = 0; nt < 4; nt++)
                    wnext[nt] = __ldg(&g_W2f[(k8n * NB2 + wn * 4 + nt) * 32 + lane]);
#pragma unroll
                for (int nt = 0; nt < 4; nt++) {
                    uint32_t b0 = __float_as_uint(wbuf[nt].x);
                    uint32_t b1r = __float_as_uint(wbuf[nt].y);
#pragma unroll
                    for (int mt = 0; mt < 2; mt++) {
                        asm volatile(
                            "mma.sync.aligned.m16n8k8.row.col.f32.tf32.tf32.f32 "
                            "{%0,%1,%2,%3}, {%4,%5,%6,%7}, {%8,%9}, {%0,%1,%2,%3};"
                            : "+f"(c2[mt][nt][0]), "+f"(c2[mt][nt][1]),
                              "+f"(c2[mt][nt][2]), "+f"(c2[mt][nt][3])
                            : "r"(a[mt][0]), "r"(a[mt][1]),
                              "r"(a[mt][2]), "r"(a[mt][3]), "r"(b0), "r"(b1r));
                    }
                }
#pragma unroll
                for (int nt = 0; nt < 4; nt++) wbuf[nt] = wnext[nt];
            }
            // epilogue -> out
#pragma unroll
            for (int mt = 0; mt < 2; mt++) {
                const int gr0 = m0 + wm * 32 + mt * 16 + g;
#pragma unroll
                for (int nt = 0; nt < 4; nt++) {
                    int col = wn * 32 + nt * 8 + 2 * tig;
                    float bx = __ldg(b2 + col), by = __ldg(b2 + col + 1);
                    float v0 = c2[mt][nt][0] + bx, v1 = c2[mt][nt][1] + by;
                    float v2 = c2[mt][nt][2] + bx, v3 = c2[mt][nt][3] + by;
                    if (gr0 < M)
                        *(float2*)(out + (size_t)gr0 * NO + col) = make_float2(v0, v1);
                    if (gr0 + 8 < M)
                        *(float2*)(out + (size_t)(gr0 + 8) * NO + col) = make_float2(v2, v3);
                }
            }
        }
        __syncthreads();
    }
}

// ---------------------------------------------------------------------------
extern "C" void kernel_launch(void* const* d_in, const int* in_sizes, int n_in,
                              void* d_out, int out_size) {
    const float* x   = (const float*)d_in[0];
    const float* ev  = (const float*)d_in[1];
    const float* W1  = (const float*)d_in[2];
    const float* b1  = (const float*)d_in[3];
    const float* W2  = (const float*)d_in[4];
    const float* b2  = (const float*)d_in[5];
    const float* eps = (const float*)d_in[6];
    const int*  esrc = (const int*)d_in[7];
    const int*  edst = (const int*)d_in[8];
    float* out = (float*)d_out;

    // smem: As (64x132) + Hs (64x256) = 99,328 B  -> 2 CTAs/SM
    const int smemF = (BMT * SA1 + BMT * NH) * 4;

    cudaFuncSetAttribute((const void*)fused_mlp,
                         cudaFuncAttributeMaxDynamicSharedMemorySize, smemF);

    const int EB  = (N_EDGES + 255) / 256;
    const int NBk = (N_NODES + 255) / 256;

    k_zero_pack<<<NBk, 256>>>(W1, W2);
    k_hist  <<<EB, 256>>>(edst);
    k_scan1 <<<SCAN_NB, SCAN_B>>>();
    k_scan23<<<NBk, 256>>>();
    k_fill  <<<EB, 256>>>(esrc, edst, ev);

    fused_mlp<<<2 * NSM, 256, smemF>>>(x, eps, b1, b2, out, N_NODES);
}

// round 15
// speedup vs baseline: 1.1804x; 1.1804x over previous
#include <cuda_runtime.h>
#include <cstdint>

#define N_NODES 100000
#define D_IN 128
#define D_HID 256
#define D_OUT 128
#define N_EDGES 1600000
#define NSM 148
#define SCAN_B 512
#define SCAN_NB ((N_NODES + SCAN_B - 1) / SCAN_B)

// Scratch (static __device__ arrays — no runtime allocation).
__device__ float  g_AX[(size_t)N_NODES * D_IN];   // 51.2 MB (tf32-rounded)
__device__ int    g_row[N_NODES + 1];             // CSR row starts
__device__ int    g_cursor[N_NODES];              // fill cursors
__device__ int    g_part[SCAN_NB];                // scan partials
__device__ int    g_srcS[N_EDGES];                // src sorted by dst
__device__ float  g_valS[N_EDGES];                // val sorted by dst
__device__ float2 g_W1f[(D_IN  / 8) * (D_HID / 8) * 32];  // W1 fragment-packed
__device__ float2 g_W2f[(D_HID / 8) * (D_OUT / 8) * 32];  // W2 fragment-packed

__device__ __forceinline__ float f2tf32(float f) {
    uint32_t r;
    asm("cvt.rna.tf32.f32 %0, %1;" : "=r"(r) : "f"(f));
    return __uint_as_float(r);
}

// ---------------------------------------------------------------------------
// K0: zero histogram counters + pack W1/W2 into MMA B-fragment order (tf32).
// ---------------------------------------------------------------------------
__global__ void k_zero_pack(const float* __restrict__ W1,
                            const float* __restrict__ W2) {
    int i = blockIdx.x * blockDim.x + threadIdx.x;
    if (i < N_NODES) g_row[i] = 0;
    constexpr int NB1c = D_HID / 8;  // 32
    constexpr int KB1c = D_IN  / 8;  // 16
    constexpr int NB2c = D_OUT / 8;  // 16
    constexpr int KB2c = D_HID / 8;  // 32
    if (i < KB1c * NB1c * 32) {
        int l   = i & 31;
        int n8  = (i >> 5) % NB1c;
        int k8  = (i >> 5) / NB1c;
        int col = n8 * 8 + (l >> 2);
        int r0  = k8 * 8 + (l & 3);
        float2 v;
        v.x = f2tf32(__ldg(W1 + r0 * D_HID + col));
        v.y = f2tf32(__ldg(W1 + (r0 + 4) * D_HID + col));
        g_W1f[i] = v;
    }
    if (i < KB2c * NB2c * 32) {
        int l   = i & 31;
        int n8  = (i >> 5) % NB2c;
        int k8  = (i >> 5) / NB2c;
        int col = n8 * 8 + (l >> 2);
        int r0  = k8 * 8 + (l & 3);
        float2 v;
        v.x = f2tf32(__ldg(W2 + r0 * D_OUT + col));
        v.y = f2tf32(__ldg(W2 + (r0 + 4) * D_OUT + col));
        g_W2f[i] = v;
    }
}

__global__ void k_hist(const int* __restrict__ dst) {
    int e = blockIdx.x * blockDim.x + threadIdx.x;
    if (e < N_EDGES) atomicAdd(&g_row[__ldg(dst + e)], 1);
}

__global__ void k_scan1() {   // per-block exclusive scan + block totals
    __shared__ int sm[SCAN_B];
    int i = blockIdx.x * SCAN_B + threadIdx.x;
    int v = (i < N_NODES) ? g_row[i] : 0;
    sm[threadIdx.x] = v;
    __syncthreads();
    for (int off = 1; off < SCAN_B; off <<= 1) {
        int t = (threadIdx.x >= off) ? sm[threadIdx.x - off] : 0;
        __syncthreads();
        sm[threadIdx.x] += t;
        __syncthreads();
    }
    if (i < N_NODES) g_row[i] = sm[threadIdx.x] - v;   // exclusive
    if (threadIdx.x == SCAN_B - 1) g_part[blockIdx.x] = sm[SCAN_B - 1];
}

// scan of g_part folded in: every block redundantly exclusive-scans the
// SCAN_NB partials in smem (read-only on g_part -> no race), then adds base.
__global__ void k_scan23() {
    __shared__ int sp[256];
    int t = threadIdx.x;
    int v = (t < SCAN_NB) ? g_part[t] : 0;
    sp[t] = v;
    __syncthreads();
    for (int off = 1; off < 256; off <<= 1) {
        int u = (t >= off) ? sp[t - off] : 0;
        __syncthreads();
        sp[t] += u;
        __syncthreads();
    }
    __shared__ int exc[SCAN_NB];
    if (t < SCAN_NB) exc[t] = sp[t] - v;
    __syncthreads();

    int i = blockIdx.x * blockDim.x + t;
    if (i < N_NODES) {
        int val = g_row[i] + exc[i / SCAN_B];
        g_row[i] = val;
        g_cursor[i] = val;
    }
    if (i == 0) g_row[N_NODES] = N_EDGES;
}

__global__ void k_fill(const int* __restrict__ src,
                       const int* __restrict__ dst,
                       const float* __restrict__ ev) {
    int e = blockIdx.x * blockDim.x + threadIdx.x;
    if (e >= N_EDGES) return;
    int d   = __ldg(dst + e);
    int pos = atomicAdd(&g_cursor[d], 1);
    g_srcS[pos] = __ldg(src + e);
    g_valS[pos] = __ldg(ev + e);
}

// ---------------------------------------------------------------------------
// SpMM: one warp per dst node. Register float4 accumulation, fused self-loop.
// Stores tf32-pre-rounded values (saves the cvt in fused_mlp staging).
// ---------------------------------------------------------------------------
__global__ __launch_bounds__(256)
void k_spmm(const float* __restrict__ x, const float* __restrict__ eps) {
    int n = blockIdx.x * 8 + (threadIdx.x >> 5);
    if (n >= N_NODES) return;
    int lane = threadIdx.x & 31;

    const float sl = 1.0f + eps[0];
    const float* xn = x + (size_t)n * D_IN + lane * 4;
    float4 acc = *(const float4*)xn;
    acc.x *= sl; acc.y *= sl; acc.z *= sl; acc.w *= sl;

    int e   = __ldg(&g_row[n]);
    int end = __ldg(&g_row[n + 1]);

    for (; e + 1 < end; e += 2) {
        int   s0 = __ldg(g_srcS + e),     s1 = __ldg(g_srcS + e + 1);
        float v0 = __ldg(g_valS + e),     v1 = __ldg(g_valS + e + 1);
        float4 a = *(const float4*)(x + (size_t)s0 * D_IN + lane * 4);
        float4 b = *(const float4*)(x + (size_t)s1 * D_IN + lane * 4);
        acc.x += v0 * a.x + v1 * b.x;
        acc.y += v0 * a.y + v1 * b.y;
        acc.z += v0 * a.z + v1 * b.z;
        acc.w += v0 * a.w + v1 * b.w;
    }
    if (e < end) {
        int   s0 = __ldg(g_srcS + e);
        float v0 = __ldg(g_valS + e);
        float4 a = *(const float4*)(x + (size_t)s0 * D_IN + lane * 4);
        acc.x += v0 * a.x; acc.y += v0 * a.y;
        acc.z += v0 * a.z; acc.w += v0 * a.w;
    }
    float4 o;
    o.x = f2tf32(acc.x); o.y = f2tf32(acc.y);
    o.z = f2tf32(acc.z); o.w = f2tf32(acc.w);
    *(float4*)(g_AX + (size_t)n * D_IN + lane * 4) = o;
}

// ---------------------------------------------------------------------------
// Fused MLP, 2 CTAs/SM: out = (relu(AX@W1+b1))@W2 + b2.
// W1 AND W2 fragments stream from L2 (g_W1f/g_W2f) with register
// double-buffers; smem holds only As (64x132) + Hs (64x256) = 99 KB,
// so 2 CTAs co-reside per SM (16 warps) and cover each other's bubbles.
// ---------------------------------------------------------------------------
#define K1 D_IN        // 128
#define NH D_HID       // 256
#define NO D_OUT       // 128
#define BMT 64
#define SA1 (K1 + 4)   // 132
#define KB1 (K1 / 8)   // 16
#define NB1 (NH / 8)   // 32
#define KB2 (NH / 8)   // 32
#define NB2 (NO / 8)   // 16

__global__ __launch_bounds__(256, 2)
void fused_mlp(const float* __restrict__ b1,
               const float* __restrict__ b2,
               float* __restrict__ out, int M) {
    extern __shared__ float sm[];
    float* As = sm;                    // 64 x 132
    float* Hs = sm + BMT * SA1;        // 64 x 256 (swizzled)

    const int tid  = threadIdx.x;
    const int lane = tid & 31;
    const int g    = lane >> 2, tig = lane & 3;
    const int wid  = tid >> 5;
    const int wm   = wid >> 2, wn = wid & 3;

    const int nTiles = (M + BMT - 1) / BMT;

    for (int tile = blockIdx.x; tile < nTiles; tile += gridDim.x) {
        const int m0 = tile * BMT;

        // ---- Stage AX tile to smem (already tf32-rounded) ----
        for (int i = tid; i < BMT * K1 / 4; i += 256) {
            int row = i / (K1 / 4);
            int c4  = (i % (K1 / 4)) * 4;
            int gr  = m0 + row;
            float4 a = make_float4(0.f, 0.f, 0.f, 0.f);
            if (gr < M) a = *(const float4*)(g_AX + (size_t)gr * K1 + c4);
            *(float4*)(As + row * SA1 + c4) = a;
        }
        __syncthreads();

        // ================= Phase 1: H = relu(As@W1 + b1) =================
        {
            float c1[2][8][4];
#pragma unroll
            for (int mt = 0; mt < 2; mt++)
#pragma unroll
                for (int nt = 0; nt < 8; nt++) {
                    c1[mt][nt][0] = 0.f; c1[mt][nt][1] = 0.f;
                    c1[mt][nt][2] = 0.f; c1[mt][nt][3] = 0.f;
                }
            const int rbase = wm * 32 + g;

            float2 wbuf[8], wnext[8];
#pragma unroll
            for (int nt = 0; nt < 8; nt++)
                wbuf[nt] = __ldg(&g_W1f[(0 * NB1 + wn * 8 + nt) * 32 + lane]);

#pragma unroll 2
            for (int k8 = 0; k8 < KB1; k8++) {
                const int kk = k8 * 8;
                uint32_t a[2][4];
#pragma unroll
                for (int mt = 0; mt < 2; mt++) {
                    int r0 = rbase + mt * 16;
                    a[mt][0] = __float_as_uint(As[ r0      * SA1 + kk     + tig]);
                    a[mt][1] = __float_as_uint(As[(r0 + 8) * SA1 + kk     + tig]);
                    a[mt][2] = __float_as_uint(As[ r0      * SA1 + kk + 4 + tig]);
                    a[mt][3] = __float_as_uint(As[(r0 + 8) * SA1 + kk + 4 + tig]);
                }
                int k8n = (k8 + 1 < KB1) ? k8 + 1 : k8;
#pragma unroll
                for (int nt = 0; nt < 8; nt++)
                    wnext[nt] = __ldg(&g_W1f[(k8n * NB1 + wn * 8 + nt) * 32 + lane]);
#pragma unroll
                for (int nt = 0; nt < 8; nt++) {
                    uint32_t b0 = __float_as_uint(wbuf[nt].x);
                    uint32_t b1r = __float_as_uint(wbuf[nt].y);
#pragma unroll
                    for (int mt = 0; mt < 2; mt++) {
                        asm volatile(
                            "mma.sync.aligned.m16n8k8.row.col.f32.tf32.tf32.f32 "
                            "{%0,%1,%2,%3}, {%4,%5,%6,%7}, {%8,%9}, {%0,%1,%2,%3};"
                            : "+f"(c1[mt][nt][0]), "+f"(c1[mt][nt][1]),
                              "+f"(c1[mt][nt][2]), "+f"(c1[mt][nt][3])
                            : "r"(a[mt][0]), "r"(a[mt][1]),
                              "r"(a[mt][2]), "r"(a[mt][3]), "r"(b0), "r"(b1r));
                    }
                }
#pragma unroll
                for (int nt = 0; nt < 8; nt++) wbuf[nt] = wnext[nt];
            }
            // relu + bias -> Hs (tf32, swizzled: phys col = col ^ ((row&7)<<2))
#pragma unroll
            for (int mt = 0; mt < 2; mt++) {
#pragma unroll
                for (int nt = 0; nt < 8; nt++) {
                    int col = wn * 64 + nt * 8 + 2 * tig;
                    float bx = __ldg(b1 + col), by = __ldg(b1 + col + 1);
                    float v0 = fmaxf(c1[mt][nt][0] + bx, 0.f);
                    float v1 = fmaxf(c1[mt][nt][1] + by, 0.f);
                    float v2 = fmaxf(c1[mt][nt][2] + bx, 0.f);
                    float v3 = fmaxf(c1[mt][nt][3] + by, 0.f);
                    int r0 = wm * 32 + mt * 16 + g;      // row&7 == g
                    int r1 = r0 + 8;
                    *(float2*)(Hs + r0 * NH + (col ^ (g << 2))) =
                        make_float2(f2tf32(v0), f2tf32(v1));
                    *(float2*)(Hs + r1 * NH + (col ^ (g << 2))) =
                        make_float2(f2tf32(v2), f2tf32(v3));
                }
            }
        }
        __syncthreads();

        // ================= Phase 2: out = Hs@W2 + b2 =================
        {
            float c2[2][4][4];
#pragma unroll
            for (int mt = 0; mt < 2; mt++)
#pragma unroll
                for (int nt = 0; nt < 4; nt++) {
                    c2[mt][nt][0] = 0.f; c2[mt][nt][1] = 0.f;
                    c2[mt][nt][2] = 0.f; c2[mt][nt][3] = 0.f;
                }
            const int rbase = wm * 32 + g;

            float2 wbuf[4], wnext[4];
#pragma unroll
            for (int nt = 0; nt < 4; nt++)
                wbuf[nt] = __ldg(&g_W2f[(0 * NB2 + wn * 4 + nt) * 32 + lane]);

#pragma unroll 4
            for (int k8 = 0; k8 < KB2; k8++) {
                const int kk = k8 * 8;
                uint32_t a[2][4];
#pragma unroll
                for (int mt = 0; mt < 2; mt++) {
                    int r0 = rbase + mt * 16;
                    int sw = (g << 2);
                    a[mt][0] = __float_as_uint(Hs[ r0      * NH + ((kk     + tig) ^ sw)]);
                    a[mt][1] = __float_as_uint(Hs[(r0 + 8) * NH + ((kk     + tig) ^ sw)]);
                    a[mt][2] = __float_as_uint(Hs[ r0      * NH + ((kk + 4 + tig) ^ sw)]);
                    a[mt][3] = __float_as_uint(Hs[(r0 + 8) * NH + ((kk + 4 + tig) ^ sw)]);
                }
                int k8n = (k8 + 1 < KB2) ? k8 + 1 : k8;
#pragma unroll
                for (int nt = 0; nt < 4; nt++)
                    wnext[nt] = __ldg(&g_W2f[(k8n * NB2 + wn * 4 + nt) * 32 + lane]);
#pragma unroll
                for (int nt = 0; nt < 4; nt++) {
                    uint32_t b0 = __float_as_uint(wbuf[nt].x);
                    uint32_t b1r = __float_as_uint(wbuf[nt].y);
#pragma unroll
                    for (int mt = 0; mt < 2; mt++) {
                        asm volatile(
                            "mma.sync.aligned.m16n8k8.row.col.f32.tf32.tf32.f32 "
                            "{%0,%1,%2,%3}, {%4,%5,%6,%7}, {%8,%9}, {%0,%1,%2,%3};"
                            : "+f"(c2[mt][nt][0]), "+f"(c2[mt][nt][1]),
                              "+f"(c2[mt][nt][2]), "+f"(c2[mt][nt][3])
                            : "r"(a[mt][0]), "r"(a[mt][1]),
                              "r"(a[mt][2]), "r"(a[mt][3]), "r"(b0), "r"(b1r));
                    }
                }
#pragma unroll
                for (int nt = 0; nt < 4; nt++) wbuf[nt] = wnext[nt];
            }
            // epilogue -> out
#pragma unroll
            for (int mt = 0; mt < 2; mt++) {
                const int gr0 = m0 + wm * 32 + mt * 16 + g;
#pragma unroll
                for (int nt = 0; nt < 4; nt++) {
                    int col = wn * 32 + nt * 8 + 2 * tig;
                    float bx = __ldg(b2 + col), by = __ldg(b2 + col + 1);
                    float v0 = c2[mt][nt][0] + bx, v1 = c2[mt][nt][1] + by;
                    float v2 = c2[mt][nt][2] + bx, v3 = c2[mt][nt][3] + by;
                    if (gr0 < M)
                        *(float2*)(out + (size_t)gr0 * NO + col) = make_float2(v0, v1);
                    if (gr0 + 8 < M)
                        *(float2*)(out + (size_t)(gr0 + 8) * NO + col) = make_float2(v2, v3);
                }
            }
        }
        __syncthreads();
    }
}

// ---------------------------------------------------------------------------
extern "C" void kernel_launch(void* const* d_in, const int* in_sizes, int n_in,
                              void* d_out, int out_size) {
    const float* x   = (const float*)d_in[0];
    const float* ev  = (const float*)d_in[1];
    const float* W1  = (const float*)d_in[2];
    const float* b1  = (const float*)d_in[3];
    const float* W2  = (const float*)d_in[4];
    const float* b2  = (const float*)d_in[5];
    const float* eps = (const float*)d_in[6];
    const int*  esrc = (const int*)d_in[7];
    const int*  edst = (const int*)d_in[8];
    float* out = (float*)d_out;

    // smem: As (64x132) + Hs (64x256) = 99,328 B  -> 2 CTAs/SM
    const int smemF = (BMT * SA1 + BMT * NH) * 4;

    cudaFuncSetAttribute((const void*)fused_mlp,
                         cudaFuncAttributeMaxDynamicSharedMemorySize, smemF);

    const int EB  = (N_EDGES + 255) / 256;
    const int NBk = (N_NODES + 255) / 256;

    k_zero_pack<<<NBk, 256>>>(W1, W2);
    k_hist  <<<EB, 256>>>(edst);
    k_scan1 <<<SCAN_NB, SCAN_B>>>();
    k_scan23<<<NBk, 256>>>();
    k_fill  <<<EB, 256>>>(esrc, edst, ev);
    k_spmm  <<<(N_NODES + 7) / 8, 256>>>(x, eps);

    fused_mlp<<<2 * NSM, 256, smemF>>>(b1, b2, out, N_NODES);
}